// round 14
// baseline (speedup 1.0000x reference)
#include <cuda_runtime.h>
#include <cuda_fp16.h>
#include <cstdint>

#define NROWS 87382          // 87381 nodes + duplicated root
#define NLEAF 65536
#define LEAF_SOFF 21845

#define GN 1792
#define GK 1024

// ---- fp16 mma GEMM: CTA 128x64, 8 warps (32x32), KC=32, 4-stage, 3 CTAs/SM ----
#define TM 128
#define TN 64
#define KC 32
#define NCH (GK/KC)           // 32
#define NST 4
#define ROWW 20               // uint32 words per row: 16 data (32 halves) + 4 pad
#define A_OFF 0
#define U_OFF (128*ROWW)
#define STG (192*ROWW)        // 3840 words per stage
#define SMEMB (NST*STG*4)     // 61440 B
#define CPAD 72               // halves per staged C row (144B, 16B-aligned)

// ---------------- device scratch (no allocations allowed) ----------------
__device__ float g_T_iou[1000*768];
__device__ float g_T_f[1000*256];
__device__ float g_uiou0[768];
__device__ float g_uf0[1024];
__device__ float g_lH[1000*256];                       // leaf h per symbol (fp32, attn)
__device__ float g_lC[1000*256];                       // leaf c per symbol
__device__ __align__(16) __half g_lHh[1000*256];       // leaf h per symbol (fp16, gemm A)
__device__ float g_U[1792*1024];                       // packed U fp32 (small_gemm)
__device__ __align__(16) __half g_Uh[1792*1024];       // packed U fp16 (mma)
__device__ float g_enc_h[(size_t)NROWS*256];           // interior rows + dup root
__device__ __align__(16) __half g_hH[(size_t)NROWS*256]; // fp16 interior h (gemm A)
__device__ float g_cA[(size_t)16384*256];
__device__ float g_cB[(size_t)16384*256];
__device__ __align__(16) __half g_G[(size_t)16384*1792];  // gate preactivations (fp16)
__device__ float g_w[4*256];
__device__ float g_sum[4];
__device__ float g_hn_r[256];
__device__ float g_cn_r[256];
__device__ float g_qk_r[256];
__device__ float g_hn_c[4*256];
__device__ float g_cn_c[4*256];
__device__ float g_qk_c[4*256];
__device__ float g_hr[256];
__device__ float g_rows[20*256];

__device__ __forceinline__ float sigf(float x){ return 1.f/(1.f+__expf(-x)); }
__device__ __forceinline__ float tanhfast(float x){ return 1.f - 2.f/(__expf(2.f*x)+1.f); }

__device__ __forceinline__ void cpasync16p(uint32_t dst, const void* src, bool p){
    int sz = p ? 16 : 0;
    asm volatile("cp.async.cg.shared.global [%0], [%1], 16, %2;\n"
                 :: "r"(dst), "l"(src), "r"(sz));
}
__device__ __forceinline__ void cp_commit(){ asm volatile("cp.async.commit_group;\n"); }
template<int N> __device__ __forceinline__ void cp_wait(){ asm volatile("cp.async.wait_group %0;\n" :: "n"(N)); }

__device__ __forceinline__ void mma_f16(float* d, const uint32_t* a, const uint32_t* b){
    asm volatile(
        "mma.sync.aligned.m16n8k16.row.col.f32.f16.f16.f32 "
        "{%0,%1,%2,%3}, {%4,%5,%6,%7}, {%8,%9}, {%0,%1,%2,%3};"
        : "+f"(d[0]), "+f"(d[1]), "+f"(d[2]), "+f"(d[3])
        : "r"(a[0]), "r"(a[1]), "r"(a[2]), "r"(a[3]), "r"(b[0]), "r"(b[1]));
}

__device__ __forceinline__ void ldsm4(uint32_t& r0, uint32_t& r1, uint32_t& r2, uint32_t& r3,
                                      uint32_t addr){
    asm volatile("ldmatrix.sync.aligned.m8n8.x4.shared.b16 {%0,%1,%2,%3}, [%4];"
        : "=r"(r0), "=r"(r1), "=r"(r2), "=r"(r3) : "r"(addr));
}

// warp-dot helper: 256-float dot (a in smem, w in gmem), lane-strided float4
__device__ __forceinline__ float wdot256(const float4* __restrict__ w,
                                         const float4* __restrict__ a, int lane){
    float acc = 0.f;
    #pragma unroll
    for (int i = 0; i < 2; i++) {
        float4 wv = w[lane + i*32];
        float4 av = a[lane + i*32];
        acc += wv.x*av.x + wv.y*av.y + wv.z*av.z + wv.w*av.w;
    }
    #pragma unroll
    for (int off = 16; off; off >>= 1) acc += __shfl_xor_sync(0xffffffffu, acc, off);
    return acc;
}

// ---------------- fp16 GEMM: G[M,1792] = A[M,1024] @ Uh^T (128x64, 3 CTA/SM) ----------------
__global__ void __launch_bounds__(256, 3) gemm_f16(
    const __half* __restrict__ Ah, const int* __restrict__ aidx,
    __half* __restrict__ C, int M)
{
    extern __shared__ uint32_t smw[];

    const int tid  = threadIdx.x;
    const int lane = tid & 31;
    const int wid  = tid >> 5;
    const int warp_m = wid & 3;          // 32-row slab
    const int warp_n = wid >> 2;         // 32-col slab

    const int m0 = blockIdx.y * TM;
    const int n0 = blockIdx.x * TN;

    // loader roles: threads 0-127 -> A rows, 128-191 -> U rows, 192-255 idle
    const int role = tid >> 7;           // 0: A, 1: U/idle
    const int lrow = tid & 127;
    const bool arow_ok = (m0 + lrow) < M;
    const bool urow_ok = (role == 1) && (lrow < 64);

    uint32_t sb = (uint32_t)__cvta_generic_to_shared(smw);
    uint32_t dst = sb + ((role ? U_OFF : A_OFF) + (role ? (lrow & 63) : lrow)*ROWW)*4;

    const __half* Urow = g_Uh + (size_t)(n0 + (lrow & 63))*GK;

    const int mi = lane >> 3, rr = lane & 7;
    const uint32_t loff = (uint32_t)((((mi & 1)*8 + rr)*ROWW)*4 + (mi >> 1)*16);

    auto issue = [&](int ch, int slot){
        uint32_t so = slot * (STG*4);
        if (role == 0) {
            // unique dst per thread; zero-fill beyond M is intended
            const __half* gsrc;
            if (aidx) {
                int a = ch >> 3;
                int id = arow_ok ? __ldg(aidx + (size_t)(m0 + lrow)*4 + a) : 0;
                gsrc = Ah + (size_t)id*256 + ((ch*KC) & 255);
            } else {
                gsrc = Ah + (size_t)(m0 + lrow)*GK + ch*KC;
            }
            #pragma unroll
            for (int c = 0; c < 4; c++) cpasync16p(so + dst + c*16, gsrc + c*8, arow_ok);
        } else if (urow_ok) {
            // idle U threads (192-255) must NOT issue: their dst would alias
            // live U rows and cp.async size-0 zero-fills the destination.
            const __half* gsrc = Urow + ch*KC;
            #pragma unroll
            for (int c = 0; c < 4; c++) cpasync16p(so + dst + c*16, gsrc + c*8, true);
        }
        cp_commit();   // uniform group accounting across all threads
    };

    #pragma unroll
    for (int s = 0; s < NST-1; s++) issue(s, s);

    float acc[2][4][4];
    #pragma unroll
    for (int mt = 0; mt < 2; mt++)
        #pragma unroll
        for (int nt = 0; nt < 4; nt++)
            #pragma unroll
            for (int q = 0; q < 4; q++) acc[mt][nt][q] = 0.f;

    for (int i = 0; i < NCH; i++) {
        cp_wait<NST-2>();
        __syncthreads();

        int nx = i + NST - 1;
        if (nx < NCH) issue(nx, nx % NST);
        else cp_commit();

        const uint32_t stg = sb + (i % NST)*(STG*4);

        #pragma unroll
        for (int ks = 0; ks < 2; ks++) {
            const uint32_t kb = ks*32;
            uint32_t af[2][4], bf[4][2];
            #pragma unroll
            for (int mt = 0; mt < 2; mt++)
                ldsm4(af[mt][0], af[mt][1], af[mt][2], af[mt][3],
                      stg + (uint32_t)((warp_m*32 + mt*16)*ROWW)*4 + kb + loff);
            #pragma unroll
            for (int ntp = 0; ntp < 2; ntp++) {
                uint32_t r0, r1, r2, r3;
                ldsm4(r0, r1, r2, r3,
                      stg + (uint32_t)(U_OFF + (warp_n*32 + ntp*16)*ROWW)*4 + kb + loff);
                bf[2*ntp][0]   = r0;
                bf[2*ntp+1][0] = r1;
                bf[2*ntp][1]   = r2;
                bf[2*ntp+1][1] = r3;
            }
            #pragma unroll
            for (int mt = 0; mt < 2; mt++)
                #pragma unroll
                for (int nt = 0; nt < 4; nt++)
                    mma_f16(acc[mt][nt], af[mt], bf[nt]);
        }
    }

    // ---- coalesced epilogue: stage 128x64 fp16 tile, then 16B stores ----
    cp_wait<0>();
    __syncthreads();
    __half* Cs = reinterpret_cast<__half*>(smw);
    const int g  = lane >> 2;
    const int tq = lane & 3;
    #pragma unroll
    for (int mt = 0; mt < 2; mt++) {
        int rm = warp_m*32 + mt*16 + g;
        #pragma unroll
        for (int nt = 0; nt < 4; nt++) {
            int cn = warp_n*32 + nt*8 + tq*2;
            *reinterpret_cast<__half2*>(Cs + rm*CPAD + cn)
                = __floats2half2_rn(acc[mt][nt][0], acc[mt][nt][1]);
            *reinterpret_cast<__half2*>(Cs + (rm+8)*CPAD + cn)
                = __floats2half2_rn(acc[mt][nt][2], acc[mt][nt][3]);
        }
    }
    __syncthreads();
    #pragma unroll
    for (int it = 0; it < 4; it++) {
        int idx = it*256 + tid;          // 0..1023 (128 rows x 8 uint4)
        int r  = idx >> 3;
        int cc = (idx & 7) * 8;
        if (m0 + r < M) {
            const uint4 v = *reinterpret_cast<const uint4*>(Cs + r*CPAD + cc);
            *reinterpret_cast<uint4*>(C + (size_t)(m0+r)*GN + n0 + cc) = v;
        }
    }
}

// ---------------- merged prep GEMM: T_iou + T_f ----------------
__global__ void __launch_bounds__(256, 2) prep_tables(
    const float* __restrict__ emb,
    const float* __restrict__ W_iou, const float* __restrict__ b_iou,
    const float* __restrict__ b_uiou,
    const float* __restrict__ W_f,   const float* __restrict__ b_wf)
{
    __shared__ float As[16][128];
    __shared__ float Ws[16][128];
    const int tid  = threadIdx.x;
    const int m0   = blockIdx.y * 128;

    const float* W; const float* bias; const float* bias2; float* Cc; int N; int n0;
    if (blockIdx.x < 6) { W = W_iou; bias = b_iou; bias2 = b_uiou; Cc = g_T_iou; N = 768; n0 = blockIdx.x*128; }
    else                { W = W_f;   bias = b_wf;  bias2 = nullptr; Cc = g_T_f; N = 256; n0 = (blockIdx.x-6)*128; }

    const int M = 1000, K = 256;
    const int trow = (tid >> 4) << 3;
    const int tcol = (tid & 15) << 3;
    const int lm   = tid >> 2;
    const int lk   = (tid & 3) << 2;

    float acc[8][8];
    #pragma unroll
    for (int i = 0; i < 8; i++)
        #pragma unroll
        for (int j = 0; j < 8; j++) acc[i][j] = 0.f;

    for (int k0 = 0; k0 < K; k0 += 16) {
        #pragma unroll
        for (int h = 0; h < 2; h++) {
            int m = m0 + lm + h*64;
            float4 v = make_float4(0.f,0.f,0.f,0.f);
            if (m < M) v = *reinterpret_cast<const float4*>(emb + (size_t)m*K + k0 + lk);
            As[lk+0][lm+h*64] = v.x; As[lk+1][lm+h*64] = v.y;
            As[lk+2][lm+h*64] = v.z; As[lk+3][lm+h*64] = v.w;

            int n = n0 + lm + h*64;
            float4 w = make_float4(0.f,0.f,0.f,0.f);
            if (n < N) w = *reinterpret_cast<const float4*>(W + (size_t)n*K + k0 + lk);
            Ws[lk+0][lm+h*64] = w.x; Ws[lk+1][lm+h*64] = w.y;
            Ws[lk+2][lm+h*64] = w.z; Ws[lk+3][lm+h*64] = w.w;
        }
        __syncthreads();
        #pragma unroll
        for (int kk = 0; kk < 16; kk++) {
            float ra[8], rw[8];
            #pragma unroll
            for (int i = 0; i < 8; i++) ra[i] = As[kk][trow+i];
            #pragma unroll
            for (int j = 0; j < 8; j++) rw[j] = Ws[kk][tcol+j];
            #pragma unroll
            for (int i = 0; i < 8; i++)
                #pragma unroll
                for (int j = 0; j < 8; j++) acc[i][j] += ra[i]*rw[j];
        }
        __syncthreads();
    }
    #pragma unroll
    for (int i = 0; i < 8; i++) {
        int m = m0 + trow + i;
        if (m >= M) break;
        #pragma unroll
        for (int j = 0; j < 8; j++) {
            int n = n0 + tcol + j;
            float b = bias[n];
            if (bias2) b += bias2[n];
            Cc[(size_t)m*N + n] = acc[i][j] + b;
        }
    }
}

// ---------------- pack U + leaf constants ----------------
__global__ void pack_U_consts(const float* __restrict__ U_iou, const float* __restrict__ U_f,
                              const float* __restrict__ h0,    const float* __restrict__ b_uf)
{
    int idx = blockIdx.x * 256 + threadIdx.x;
    int r = idx / 256;
    int c4 = idx % 256;
    const float4* srcp;
    if (r < 768) srcp = reinterpret_cast<const float4*>(U_iou + (size_t)r*1024) + c4;
    else         srcp = reinterpret_cast<const float4*>(U_f   + (size_t)(r-768)*1024) + c4;
    float4 v = *srcp;
    reinterpret_cast<float4*>(g_U + (size_t)r*1024)[c4] = v;
    size_t o = (size_t)r*1024 + c4*4;
    g_Uh[o+0] = __float2half(v.x); g_Uh[o+1] = __float2half(v.y);
    g_Uh[o+2] = __float2half(v.z); g_Uh[o+3] = __float2half(v.w);

    if (blockIdx.x < 224) {
        int lane = threadIdx.x & 31;
        int w = blockIdx.x * 8 + (threadIdx.x >> 5);
        const float* u = (w < 768) ? (U_iou + (size_t)w*1024) : (U_f + (size_t)(w-768)*1024);
        const float4* u4 = reinterpret_cast<const float4*>(u);
        const float4* h4 = reinterpret_cast<const float4*>(h0);
        float acc = 0.f;
        #pragma unroll
        for (int i = 0; i < 8; i++) {
            float4 uv = u4[lane + i*32];
            float4 hv = h4[lane + i*32];
            acc += uv.x*hv.x + uv.y*hv.y + uv.z*hv.z + uv.w*hv.w;
        }
        #pragma unroll
        for (int off = 16; off; off >>= 1) acc += __shfl_xor_sync(0xffffffffu, acc, off);
        if (lane == 0) {
            if (w < 768) g_uiou0[w] = acc;
            else g_uf0[w-768] = acc + b_uf[w-768];
        }
    }
}

// ---------------- small-M GEMM (B<=64): warp-per-column, fp32, fp16 out ----------------
__global__ void small_gemm(const float* __restrict__ A, __half* __restrict__ C)
{
    __shared__ float sh[1024];
    int tid = threadIdx.x, lane = tid & 31, wid = tid >> 5;
    int m = blockIdx.y;
    for (int i = tid; i < 256; i += 256)
        reinterpret_cast<float4*>(sh)[i] = reinterpret_cast<const float4*>(A + (size_t)m*1024)[i];
    __syncthreads();
    int ntile = blockIdx.x * 256;
    for (int n = ntile + wid; n < ntile + 256 && n < GN; n += 8) {
        const float4* u = reinterpret_cast<const float4*>(g_U + (size_t)n*1024);
        float acc = 0.f;
        #pragma unroll
        for (int i = 0; i < 8; i++) {
            float4 uv = u[lane + i*32];
            float4 hv = reinterpret_cast<const float4*>(sh)[lane + i*32];
            acc += uv.x*hv.x + uv.y*hv.y + uv.z*hv.z + uv.w*hv.w;
        }
        #pragma unroll
        for (int off = 16; off; off >>= 1) acc += __shfl_xor_sync(0xffffffffu, acc, off);
        if (lane == 0) C[(size_t)m*GN + n] = __float2half(acc);
    }
}

// ---------------- per-symbol leaf tables ----------------
__global__ void leaf_tab(const float* __restrict__ c0)
{
    int s = blockIdx.x, j = threadIdx.x;
    const float* T = g_T_iou + (size_t)s*768;
    float i = sigf(T[j]       + g_uiou0[j]);
    float o = sigf(T[256+j]   + g_uiou0[256+j]);
    float u = tanhfast(T[512+j] + g_uiou0[512+j]);
    float tf = g_T_f[(size_t)s*256 + j];
    float c = i*u;
    #pragma unroll
    for (int a = 0; a < 4; a++) {
        float f = sigf(g_uf0[a*256+j] + tf);
        c += f * c0[a*256+j];
    }
    float h = o * tanhfast(c);
    g_lH[(size_t)s*256 + j]  = h;
    g_lHh[(size_t)s*256 + j] = __float2half(h);
    g_lC[(size_t)s*256 + j]  = c;
}

// ---------------- interior level: combine GEMM result (fp16) + gates ----------------
__global__ void level_ew(const int* __restrict__ src, int soff,
                         const int* __restrict__ leafsrc,
                         const float* __restrict__ cprev, float* __restrict__ cout,
                         int rowoff, int dup, const float* __restrict__ b_uf)
{
    int b = blockIdx.x, j = threadIdx.x;
    int id = src[soff + b];
    const float* T = g_T_iou + (size_t)id*768;
    const __half* G = g_G + (size_t)b*1792;
    float i = sigf(__half2float(G[j])       + T[j]);
    float o = sigf(__half2float(G[256+j])   + T[256+j]);
    float u = tanhfast(__half2float(G[512+j]) + T[512+j]);
    float tf = g_T_f[(size_t)id*256 + j];
    float c = i*u;
    #pragma unroll
    for (int a = 0; a < 4; a++) {
        float f = sigf(__half2float(G[768 + a*256 + j]) + b_uf[a*256+j] + tf);
        float cv;
        if (leafsrc) cv = g_lC[(size_t)__ldg(leafsrc + 4*b + a)*256 + j];
        else         cv = cprev[(size_t)(4*b+a)*256 + j];
        c += f * cv;
    }
    float h = o * tanhfast(c);
    size_t row = (size_t)(rowoff + b);
    g_enc_h[row*256 + j] = h;
    g_hH[row*256 + j]    = __float2half(h);
    cout[(size_t)b*256 + j] = c;
    if (dup) g_enc_h[(row+1)*256 + j] = h;   // duplicate root row
}

// ---------------- decoder LSTM cell + fused q@Wq@Wk (coalesced warp-dots) ----------------
__global__ void dec_prep(const float* __restrict__ emb, const int* __restrict__ tgt, int tbase,
                         const float* __restrict__ h_last, const float* __restrict__ c_last,
                         const float* __restrict__ W_ih, const float* __restrict__ b_ih,
                         const float* __restrict__ W_hh, const float* __restrict__ b_hh,
                         const float* __restrict__ Wq,   const float* __restrict__ Wk,
                         float* __restrict__ hn_out, float* __restrict__ cn_out,
                         float* __restrict__ qk_out)
{
    __shared__ float sx[256], sh[256], sg[1024], shn[256], sq[256];
    int j = threadIdx.x, bb = blockIdx.x;
    int warp = j >> 5, lane = j & 31;

    #pragma unroll
    for (int i = 0; i < 4; i++) g_w[i*256 + j] = 0.f;
    if (j < 4) g_sum[j] = 0.f;

    int sym = tgt[tbase + bb];
    sx[j] = emb[(size_t)sym*256 + j];
    sh[j] = h_last[j];
    __syncthreads();

    for (int r = warp; r < 1024; r += 8) {
        float acc = wdot256(reinterpret_cast<const float4*>(W_ih + (size_t)r*256),
                            reinterpret_cast<const float4*>(sx), lane)
                  + wdot256(reinterpret_cast<const float4*>(W_hh + (size_t)r*256),
                            reinterpret_cast<const float4*>(sh), lane);
        if (lane == 0) sg[r] = acc + b_ih[r] + b_hh[r];
    }
    __syncthreads();

    float cn = sigf(sg[256+j])*c_last[j] + sigf(sg[j])*tanhfast(sg[512+j]);
    float hn = sigf(sg[768+j])*tanhfast(cn);
    shn[j] = hn;
    hn_out[bb*256+j] = hn;
    cn_out[bb*256+j] = cn;
    __syncthreads();

    for (int r = warp; r < 256; r += 8) {
        float acc = wdot256(reinterpret_cast<const float4*>(Wq + (size_t)r*256),
                            reinterpret_cast<const float4*>(shn), lane);
        if (lane == 0) sq[r] = acc;
    }
    __syncthreads();

    float qk = 0.f;
    for (int k = 0; k < 256; k++) qk += sq[k]*Wk[(size_t)k*256 + j];
    qk_out[bb*256+j] = qk;
}

// row pointer: leaves gathered from the per-symbol table, interior from enc_h
__device__ __forceinline__ const float* attn_row(int r, const int* __restrict__ src){
    if (r < NLEAF) return g_lH + (size_t)__ldg(src + LEAF_SOFF + r)*256;
    return g_enc_h + (size_t)r*256;
}

// ---------------- one-pass attention ----------------
#define FROWS 512
__global__ void attn_fused(const float* __restrict__ qk, int B, const int* __restrict__ src)
{
    __shared__ float sqk[4*256];
    __shared__ float swsum[8][256];
    __shared__ float sesum[8][4];
    int tid = threadIdx.x;
    for (int i = tid; i < B*256; i += 256) sqk[i] = qk[i];
    __syncthreads();
    int warp = tid >> 5, lane = tid & 31;
    int start = blockIdx.x * FROWS;
    int end = min(NROWS, start + FROWS);

    float wacc[4][8];
    float esum[4] = {0.f, 0.f, 0.f, 0.f};
    #pragma unroll
    for (int b = 0; b < 4; b++)
        #pragma unroll
        for (int q = 0; q < 8; q++) wacc[b][q] = 0.f;

    for (int r = start + warp; r < end; r += 8) {
        const float4* eh = reinterpret_cast<const float4*>(attn_row(r, src)) + lane*2;
        float4 v0 = eh[0], v1 = eh[1];
        #pragma unroll 4
        for (int b = 0; b < 4; b++) {
            if (b >= B) break;
            const float* q = sqk + b*256 + lane*8;
            float s = v0.x*q[0]+v0.y*q[1]+v0.z*q[2]+v0.w*q[3]
                    + v1.x*q[4]+v1.y*q[5]+v1.z*q[6]+v1.w*q[7];
            #pragma unroll
            for (int off = 16; off; off >>= 1) s += __shfl_xor_sync(0xffffffffu, s, off);
            float e = __expf(s);
            if (lane == 0) esum[b] += e;
            wacc[b][0] += e*v0.x; wacc[b][1] += e*v0.y;
            wacc[b][2] += e*v0.z; wacc[b][3] += e*v0.w;
            wacc[b][4] += e*v1.x; wacc[b][5] += e*v1.y;
            wacc[b][6] += e*v1.z; wacc[b][7] += e*v1.w;
        }
    }
    if (lane == 0)
        #pragma unroll
        for (int b = 0; b < 4; b++) sesum[warp][b] = esum[b];

    for (int b = 0; b < B; b++) {
        __syncthreads();
        #pragma unroll
        for (int q = 0; q < 8; q++) swsum[warp][lane*8 + q] = wacc[b][q];
        __syncthreads();
        float s = 0.f;
        #pragma unroll
        for (int w = 0; w < 8; w++) s += swsum[w][tid];
        atomicAdd(&g_w[b*256 + tid], s);
    }
    __syncthreads();
    if (tid < B) {
        float s = 0.f;
        #pragma unroll
        for (int w = 0; w < 8; w++) s += sesum[w][tid];
        atomicAdd(&g_sum[tid], s);
    }
}

// ---------------- decoder finalize (coalesced warp-dots) ----------------
__global__ void dec_fin(const float* __restrict__ hn, int is_root,
                        const float* __restrict__ Wv, const float* __restrict__ linW,
                        const float* __restrict__ linb, const float* __restrict__ pos)
{
    __shared__ float sfull[512];              // [hn | ctx]
    __shared__ float swb[256], sho[256];
    int b = blockIdx.x, j = threadIdx.x;
    int warp = j >> 5, lane = j & 31;
    swb[j] = g_w[b*256+j] / g_sum[b];
    sfull[j] = hn[b*256+j];
    __syncthreads();

    for (int r = warp; r < 256; r += 8) {
        float acc = wdot256(reinterpret_cast<const float4*>(Wv + (size_t)r*256),
                            reinterpret_cast<const float4*>(swb), lane);
        if (lane == 0) sfull[256 + r] = acc;
    }
    __syncthreads();

    for (int r = warp; r < 256; r += 8) {
        const float4* lw = reinterpret_cast<const float4*>(linW + (size_t)r*512);
        const float4* a4 = reinterpret_cast<const float4*>(sfull);
        float acc = 0.f;
        #pragma unroll
        for (int i = 0; i < 4; i++) {
            float4 wv = lw[lane + i*32];
            float4 av = a4[lane + i*32];
            acc += wv.x*av.x + wv.y*av.y + wv.z*av.z + wv.w*av.w;
        }
        #pragma unroll
        for (int off = 16; off; off >>= 1) acc += __shfl_xor_sync(0xffffffffu, acc, off);
        if (lane == 0) sho[r] = acc;
    }
    __syncthreads();

    float ho = sho[j] + linb[j];
    if (is_root) {
        g_hr[j] = ho;
        #pragma unroll
        for (int a = 0; a < 4; a++) g_rows[a*256+j] = ho + pos[a*256+j];
    } else {
        #pragma unroll
        for (int a = 0; a < 4; a++) g_rows[(4 + b*4 + a)*256 + j] = ho + pos[a*256+j];
    }
}

// ---------------- vocab projection (warp per output, n split 4-way) ----------------
__global__ void out_proj(const float* __restrict__ Wout, const float* __restrict__ bout,
                         float* __restrict__ out)
{
    __shared__ float sr[256];
    int j = threadIdx.x;
    int m = blockIdx.y;
    int warp = j >> 5, lane = j & 31;
    sr[j] = g_rows[m*256 + j];
    __syncthreads();
    int nstart = blockIdx.x * 250;
    int nend = min(1000, nstart + 250);
    for (int n = nstart + warp; n < nend; n += 8) {
        float acc = wdot256(reinterpret_cast<const float4*>(Wout + (size_t)n*256),
                            reinterpret_cast<const float4*>(sr), lane);
        if (lane == 0) out[m*1000 + n] = acc + bout[n];
    }
}

// ---------------------------------------------------------------------------
extern "C" void kernel_launch(void* const* d_in, const int* in_sizes, int n_in,
                              void* d_out, int out_size)
{
    const int*   src    = (const int*)  d_in[0];
    const int*   tgt    = (const int*)  d_in[1];
    const float* emb    = (const float*)d_in[2];
    const float* h0     = (const float*)d_in[3];
    const float* c0     = (const float*)d_in[4];
    const float* W_iou  = (const float*)d_in[5];
    const float* b_iou  = (const float*)d_in[6];
    const float* U_iou  = (const float*)d_in[7];
    const float* b_uiou = (const float*)d_in[8];
    const float* W_f    = (const float*)d_in[9];
    const float* b_wf   = (const float*)d_in[10];
    const float* U_f    = (const float*)d_in[11];
    const float* b_uf   = (const float*)d_in[12];
    const float* W_ih   = (const float*)d_in[13];
    const float* b_ih   = (const float*)d_in[14];
    const float* W_hh   = (const float*)d_in[15];
    const float* b_hh   = (const float*)d_in[16];
    const float* Wq     = (const float*)d_in[17];
    const float* Wk     = (const float*)d_in[18];
    const float* Wv     = (const float*)d_in[19];
    const float* lin_W  = (const float*)d_in[20];
    const float* lin_b  = (const float*)d_in[21];
    const float* pos    = (const float*)d_in[22];
    const float* W_out  = (const float*)d_in[23];
    const float* b_out  = (const float*)d_in[24];
    float* out = (float*)d_out;

    static bool attr_done = false;
    if (!attr_done) {
        cudaFuncSetAttribute(gemm_f16, cudaFuncAttributeMaxDynamicSharedMemorySize, SMEMB);
        attr_done = true;
    }

    float *pEnc,*pCA,*pCB;
    float *pHnR,*pCnR,*pQkR,*pHnC,*pCnC,*pQkC,*pHr;
    __half *pHH,*pLHh,*pG;
    cudaGetSymbolAddress((void**)&pEnc,  g_enc_h);
    cudaGetSymbolAddress((void**)&pHH,   g_hH);
    cudaGetSymbolAddress((void**)&pLHh,  g_lHh);
    cudaGetSymbolAddress((void**)&pCA,   g_cA);
    cudaGetSymbolAddress((void**)&pCB,   g_cB);
    cudaGetSymbolAddress((void**)&pG,    g_G);
    cudaGetSymbolAddress((void**)&pHnR,  g_hn_r);
    cudaGetSymbolAddress((void**)&pCnR,  g_cn_r);
    cudaGetSymbolAddress((void**)&pQkR,  g_qk_r);
    cudaGetSymbolAddress((void**)&pHnC,  g_hn_c);
    cudaGetSymbolAddress((void**)&pCnC,  g_cn_c);
    cudaGetSymbolAddress((void**)&pQkC,  g_qk_c);
    cudaGetSymbolAddress((void**)&pHr,   g_hr);

    static const int pow4[10] = {1,4,16,64,256,1024,4096,16384,65536,262144};
    auto rowoff = [&](int l){ return (262144 - pow4[l+1]) / 3; };
    auto soff   = [&](int l){ return (pow4[l] - 1) / 3; };

    // prep (3 launches so launch #4 = level-7 gemm — the ncu capture target)
    prep_tables<<<dim3(8, 8), 256>>>(emb, W_iou, b_iou, b_uiou, W_f, b_wf);
    pack_U_consts<<<1792, 256>>>(U_iou, U_f, h0, b_uf);
    leaf_tab<<<1000, 256>>>(c0);

    // interior levels bottom-up
    float* cprev = pCA;
    float* cout  = pCB;
    for (int l = 7; l >= 0; l--) {
        int B = pow4[l];
        if (l == 7) {
            gemm_f16<<<dim3(GN/TN, (B+TM-1)/TM), 256, SMEMB>>>(pLHh, src + LEAF_SOFF, pG, B);
            level_ew<<<B, 256>>>(src, soff(l), src + LEAF_SOFF, nullptr, cout,
                                 rowoff(l), 0, b_uf);
        } else if (B >= 256) {
            const __half* Ap = pHH + (size_t)rowoff(l+1)*256;
            gemm_f16<<<dim3(GN/TN, (B+TM-1)/TM), 256, SMEMB>>>(Ap, nullptr, pG, B);
            level_ew<<<B, 256>>>(src, soff(l), nullptr, cprev, cout,
                                 rowoff(l), 0, b_uf);
        } else {
            const float* Ap = pEnc + (size_t)rowoff(l+1)*256;
            small_gemm<<<dim3(7, B), 256>>>(Ap, pG);
            level_ew<<<B, 256>>>(src, soff(l), nullptr, cprev, cout,
                                 rowoff(l), (l == 0) ? 1 : 0, b_uf);
        }
        float* t = cprev; cprev = cout; cout = t;
    }

    int fgrid = (NROWS + FROWS - 1) / FROWS;

    // root decode step
    dec_prep<<<1, 256>>>(emb, tgt, 0, pEnc + (size_t)(NROWS-1)*256, cprev,
                         W_ih, b_ih, W_hh, b_hh, Wq, Wk, pHnR, pCnR, pQkR);
    attn_fused<<<fgrid, 256>>>(pQkR, 1, src);
    dec_fin<<<1, 256>>>(pHnR, 1, Wv, lin_W, lin_b, pos);

    // child decode step (B=4)
    dec_prep<<<4, 256>>>(emb, tgt, 1, pHr, pCnR,
                         W_ih, b_ih, W_hh, b_hh, Wq, Wk, pHnC, pCnC, pQkC);
    attn_fused<<<fgrid, 256>>>(pQkC, 4, src);
    dec_fin<<<4, 256>>>(pHnC, 0, Wv, lin_W, lin_b, pos);

    // vocab projection
    out_proj<<<dim3(4, 20), 256>>>(W_out, b_out, out);
}

// round 16
// speedup vs baseline: 1.0009x; 1.0009x over previous
#include <cuda_runtime.h>
#include <cuda_fp16.h>
#include <cstdint>

#define NROWS 87382          // 87381 nodes + duplicated root
#define NLEAF 65536
#define LEAF_SOFF 21845

#define GN 1792
#define GK 1024

// ---- fp16 mma GEMM: CTA 128x128, 8 warps (32x64), KC=32, 4-stage, 2 CTAs/SM ----
#define TM 128
#define TN 128
#define KC 32
#define NCH (GK/KC)           // 32
#define NST 4
#define ROWW 20               // uint32 words per row: 16 data (32 halves) + 4 pad
#define A_OFF 0
#define U_OFF (128*ROWW)
#define STG (256*ROWW)        // 5120 words per stage
#define SMEMB (NST*STG*4)     // 81920 B
#define CPAD 136              // halves per staged C row

// ---------------- device scratch (no allocations allowed) ----------------
__device__ float g_T_iou[1000*768];
__device__ float g_T_f[1000*256];
__device__ float g_uiou0[768];
__device__ float g_uf0[1024];
__device__ float g_lC[1000*256];                       // leaf c per symbol
__device__ __align__(16) __half g_lHh[1000*256];       // leaf h per symbol (fp16)
__device__ __align__(16) __half g_Uh[1792*1024];       // packed U fp16 (mma)
__device__ float g_enc_h[(size_t)NROWS*256];           // fp32: only root dup row used
__device__ __align__(16) __half g_hH[(size_t)NROWS*256]; // fp16 interior h (gemm A + attn)
__device__ float g_cA[(size_t)16384*256];
__device__ float g_cB[(size_t)16384*256];
__device__ __align__(16) __half g_G[(size_t)16384*1792];  // gate preactivations (fp16)
__device__ float g_w[4*256];
__device__ float g_sum[4];
__device__ float g_hn_r[256];
__device__ float g_cn_r[256];
__device__ float g_qk_r[256];
__device__ float g_hn_c[4*256];
__device__ float g_cn_c[4*256];
__device__ float g_qk_c[4*256];
__device__ float g_hr[256];
__device__ float g_rows[20*256];

__device__ __forceinline__ float sigf(float x){ return 1.f/(1.f+__expf(-x)); }
__device__ __forceinline__ float tanhfast(float x){ return 1.f - 2.f/(__expf(2.f*x)+1.f); }

__device__ __forceinline__ void cpasync16p(uint32_t dst, const void* src, bool p){
    int sz = p ? 16 : 0;
    asm volatile("cp.async.cg.shared.global [%0], [%1], 16, %2;\n"
                 :: "r"(dst), "l"(src), "r"(sz));
}
__device__ __forceinline__ void cp_commit(){ asm volatile("cp.async.commit_group;\n"); }
template<int N> __device__ __forceinline__ void cp_wait(){ asm volatile("cp.async.wait_group %0;\n" :: "n"(N)); }

__device__ __forceinline__ void mma_f16(float* d, const uint32_t* a, const uint32_t* b){
    asm volatile(
        "mma.sync.aligned.m16n8k16.row.col.f32.f16.f16.f32 "
        "{%0,%1,%2,%3}, {%4,%5,%6,%7}, {%8,%9}, {%0,%1,%2,%3};"
        : "+f"(d[0]), "+f"(d[1]), "+f"(d[2]), "+f"(d[3])
        : "r"(a[0]), "r"(a[1]), "r"(a[2]), "r"(a[3]), "r"(b[0]), "r"(b[1]));
}

__device__ __forceinline__ void ldsm4(uint32_t& r0, uint32_t& r1, uint32_t& r2, uint32_t& r3,
                                      uint32_t addr){
    asm volatile("ldmatrix.sync.aligned.m8n8.x4.shared.b16 {%0,%1,%2,%3}, [%4];"
        : "=r"(r0), "=r"(r1), "=r"(r2), "=r"(r3) : "r"(addr));
}

// warp-dot helper: 256-float dot (a in smem, w in gmem), lane-strided float4
__device__ __forceinline__ float wdot256(const float4* __restrict__ w,
                                         const float4* __restrict__ a, int lane){
    float acc = 0.f;
    #pragma unroll
    for (int i = 0; i < 2; i++) {
        float4 wv = w[lane + i*32];
        float4 av = a[lane + i*32];
        acc += wv.x*av.x + wv.y*av.y + wv.z*av.z + wv.w*av.w;
    }
    #pragma unroll
    for (int off = 16; off; off >>= 1) acc += __shfl_xor_sync(0xffffffffu, acc, off);
    return acc;
}

// ---------------- fp16 GEMM: G[M,1792] = A[M,1024] @ Uh^T (128x128, 2 CTA/SM) ----------------
__global__ void __launch_bounds__(256, 2) gemm_f16(
    const __half* __restrict__ Ah, const int* __restrict__ aidx,
    __half* __restrict__ C, int M)
{
    extern __shared__ uint32_t smw[];

    const int tid  = threadIdx.x;
    const int lane = tid & 31;
    const int wid  = tid >> 5;
    const int warp_m = wid & 3;          // 32-row slab
    const int warp_n = wid >> 2;         // 64-col slab

    const int m0 = blockIdx.y * TM;
    const int n0 = blockIdx.x * TN;

    const int role = tid >> 7;           // 0: A rows, 1: U rows
    const int lrow = tid & 127;
    const bool arow_ok = (m0 + lrow) < M;

    uint32_t sb = (uint32_t)__cvta_generic_to_shared(smw);
    uint32_t dst = sb + ((role ? U_OFF : A_OFF) + lrow*ROWW)*4;

    const __half* Urow = g_Uh + (size_t)(n0 + lrow)*GK;

    const int mi = lane >> 3, rr = lane & 7;
    const uint32_t loff = (uint32_t)((((mi & 1)*8 + rr)*ROWW)*4 + (mi >> 1)*16);

    auto issue = [&](int ch, int slot){
        uint32_t so = slot * (STG*4);
        const __half* gsrc;
        bool p;
        if (role == 0) {
            if (aidx) {
                int a = ch >> 3;
                int id = arow_ok ? __ldg(aidx + (size_t)(m0 + lrow)*4 + a) : 0;
                gsrc = Ah + (size_t)id*256 + ((ch*KC) & 255);
            } else {
                gsrc = Ah + (size_t)(m0 + lrow)*GK + ch*KC;
            }
            p = arow_ok;
        } else {
            gsrc = Urow + ch*KC;
            p = true;
        }
        #pragma unroll
        for (int c = 0; c < 4; c++) cpasync16p(so + dst + c*16, gsrc + c*8, p);
        cp_commit();
    };

    #pragma unroll
    for (int s = 0; s < NST-1; s++) issue(s, s);

    float acc[2][8][4];
    #pragma unroll
    for (int mt = 0; mt < 2; mt++)
        #pragma unroll
        for (int nt = 0; nt < 8; nt++)
            #pragma unroll
            for (int q = 0; q < 4; q++) acc[mt][nt][q] = 0.f;

    for (int i = 0; i < NCH; i++) {
        cp_wait<NST-2>();
        __syncthreads();

        int nx = i + NST - 1;
        if (nx < NCH) issue(nx, nx % NST);
        else cp_commit();

        const uint32_t stg = sb + (i % NST)*(STG*4);

        #pragma unroll
        for (int ks = 0; ks < 2; ks++) {
            const uint32_t kb = ks*32;
            uint32_t af[2][4], bf[8][2];
            #pragma unroll
            for (int mt = 0; mt < 2; mt++)
                ldsm4(af[mt][0], af[mt][1], af[mt][2], af[mt][3],
                      stg + (uint32_t)((warp_m*32 + mt*16)*ROWW)*4 + kb + loff);
            #pragma unroll
            for (int ntp = 0; ntp < 4; ntp++) {
                uint32_t r0, r1, r2, r3;
                ldsm4(r0, r1, r2, r3,
                      stg + (uint32_t)(U_OFF + (warp_n*64 + ntp*16)*ROWW)*4 + kb + loff);
                bf[2*ntp][0]   = r0;
                bf[2*ntp+1][0] = r1;
                bf[2*ntp][1]   = r2;
                bf[2*ntp+1][1] = r3;
            }
            #pragma unroll
            for (int mt = 0; mt < 2; mt++)
                #pragma unroll
                for (int nt = 0; nt < 8; nt++)
                    mma_f16(acc[mt][nt], af[mt], bf[nt]);
        }
    }

    // ---- coalesced epilogue ----
    cp_wait<0>();
    __syncthreads();
    __half* Cs = reinterpret_cast<__half*>(smw);
    const int g  = lane >> 2;
    const int tq = lane & 3;
    #pragma unroll
    for (int mt = 0; mt < 2; mt++) {
        int rm = warp_m*32 + mt*16 + g;
        #pragma unroll
        for (int nt = 0; nt < 8; nt++) {
            int cn = warp_n*64 + nt*8 + tq*2;
            *reinterpret_cast<__half2*>(Cs + rm*CPAD + cn)
                = __floats2half2_rn(acc[mt][nt][0], acc[mt][nt][1]);
            *reinterpret_cast<__half2*>(Cs + (rm+8)*CPAD + cn)
                = __floats2half2_rn(acc[mt][nt][2], acc[mt][nt][3]);
        }
    }
    __syncthreads();
    #pragma unroll
    for (int it = 0; it < 8; it++) {
        int idx = it*256 + tid;          // 0..2047
        int r  = idx >> 4;               // row 0..127
        int cc = (idx & 15) * 8;
        if (m0 + r < M) {
            const uint4 v = *reinterpret_cast<const uint4*>(Cs + r*CPAD + cc);
            *reinterpret_cast<uint4*>(C + (size_t)(m0+r)*GN + n0 + cc) = v;
        }
    }
}

// ---------------- merged prep GEMM: T_iou + T_f ----------------
__global__ void __launch_bounds__(256, 2) prep_tables(
    const float* __restrict__ emb,
    const float* __restrict__ W_iou, const float* __restrict__ b_iou,
    const float* __restrict__ b_uiou,
    const float* __restrict__ W_f,   const float* __restrict__ b_wf)
{
    __shared__ float As[16][128];
    __shared__ float Ws[16][128];
    const int tid  = threadIdx.x;
    const int m0   = blockIdx.y * 128;

    const float* W; const float* bias; const float* bias2; float* Cc; int N; int n0;
    if (blockIdx.x < 6) { W = W_iou; bias = b_iou; bias2 = b_uiou; Cc = g_T_iou; N = 768; n0 = blockIdx.x*128; }
    else                { W = W_f;   bias = b_wf;  bias2 = nullptr; Cc = g_T_f; N = 256; n0 = (blockIdx.x-6)*128; }

    const int M = 1000, K = 256;
    const int trow = (tid >> 4) << 3;
    const int tcol = (tid & 15) << 3;
    const int lm   = tid >> 2;
    const int lk   = (tid & 3) << 2;

    float acc[8][8];
    #pragma unroll
    for (int i = 0; i < 8; i++)
        #pragma unroll
        for (int j = 0; j < 8; j++) acc[i][j] = 0.f;

    for (int k0 = 0; k0 < K; k0 += 16) {
        #pragma unroll
        for (int h = 0; h < 2; h++) {
            int m = m0 + lm + h*64;
            float4 v = make_float4(0.f,0.f,0.f,0.f);
            if (m < M) v = *reinterpret_cast<const float4*>(emb + (size_t)m*K + k0 + lk);
            As[lk+0][lm+h*64] = v.x; As[lk+1][lm+h*64] = v.y;
            As[lk+2][lm+h*64] = v.z; As[lk+3][lm+h*64] = v.w;

            int n = n0 + lm + h*64;
            float4 w = make_float4(0.f,0.f,0.f,0.f);
            if (n < N) w = *reinterpret_cast<const float4*>(W + (size_t)n*K + k0 + lk);
            Ws[lk+0][lm+h*64] = w.x; Ws[lk+1][lm+h*64] = w.y;
            Ws[lk+2][lm+h*64] = w.z; Ws[lk+3][lm+h*64] = w.w;
        }
        __syncthreads();
        #pragma unroll
        for (int kk = 0; kk < 16; kk++) {
            float ra[8], rw[8];
            #pragma unroll
            for (int i = 0; i < 8; i++) ra[i] = As[kk][trow+i];
            #pragma unroll
            for (int j = 0; j < 8; j++) rw[j] = Ws[kk][tcol+j];
            #pragma unroll
            for (int i = 0; i < 8; i++)
                #pragma unroll
                for (int j = 0; j < 8; j++) acc[i][j] += ra[i]*rw[j];
        }
        __syncthreads();
    }
    #pragma unroll
    for (int i = 0; i < 8; i++) {
        int m = m0 + trow + i;
        if (m >= M) break;
        #pragma unroll
        for (int j = 0; j < 8; j++) {
            int n = n0 + tcol + j;
            float b = bias[n];
            if (bias2) b += bias2[n];
            Cc[(size_t)m*N + n] = acc[i][j] + b;
        }
    }
}

// ---------------- pack U + leaf constants ----------------
__global__ void pack_U_consts(const float* __restrict__ U_iou, const float* __restrict__ U_f,
                              const float* __restrict__ h0,    const float* __restrict__ b_uf)
{
    int idx = blockIdx.x * 256 + threadIdx.x;
    int r = idx / 256;
    int c4 = idx % 256;
    const float4* srcp;
    if (r < 768) srcp = reinterpret_cast<const float4*>(U_iou + (size_t)r*1024) + c4;
    else         srcp = reinterpret_cast<const float4*>(U_f   + (size_t)(r-768)*1024) + c4;
    float4 v = *srcp;
    size_t o = (size_t)r*1024 + c4*4;
    g_Uh[o+0] = __float2half(v.x); g_Uh[o+1] = __float2half(v.y);
    g_Uh[o+2] = __float2half(v.z); g_Uh[o+3] = __float2half(v.w);

    if (blockIdx.x < 224) {
        int lane = threadIdx.x & 31;
        int w = blockIdx.x * 8 + (threadIdx.x >> 5);
        const float* u = (w < 768) ? (U_iou + (size_t)w*1024) : (U_f + (size_t)(w-768)*1024);
        const float4* u4 = reinterpret_cast<const float4*>(u);
        const float4* h4 = reinterpret_cast<const float4*>(h0);
        float acc = 0.f;
        #pragma unroll
        for (int i = 0; i < 8; i++) {
            float4 uv = u4[lane + i*32];
            float4 hv = h4[lane + i*32];
            acc += uv.x*hv.x + uv.y*hv.y + uv.z*hv.z + uv.w*hv.w;
        }
        #pragma unroll
        for (int off = 16; off; off >>= 1) acc += __shfl_xor_sync(0xffffffffu, acc, off);
        if (lane == 0) {
            if (w < 768) g_uiou0[w] = acc;
            else g_uf0[w-768] = acc + b_uf[w-768];
        }
    }
}

// ---------------- per-symbol leaf tables (h fp16, c fp32) ----------------
__global__ void leaf_tab(const float* __restrict__ c0)
{
    int s = blockIdx.x, j = threadIdx.x;
    const float* T = g_T_iou + (size_t)s*768;
    float i = sigf(T[j]       + g_uiou0[j]);
    float o = sigf(T[256+j]   + g_uiou0[256+j]);
    float u = tanhfast(T[512+j] + g_uiou0[512+j]);
    float tf = g_T_f[(size_t)s*256 + j];
    float c = i*u;
    #pragma unroll
    for (int a = 0; a < 4; a++) {
        float f = sigf(g_uf0[a*256+j] + tf);
        c += f * c0[a*256+j];
    }
    float h = o * tanhfast(c);
    g_lHh[(size_t)s*256 + j] = __float2half(h);
    g_lC[(size_t)s*256 + j]  = c;
}

// ---------------- interior level: combine GEMM result (fp16) + gates ----------------
__global__ void level_ew(const int* __restrict__ src, int soff,
                         const int* __restrict__ leafsrc,
                         const float* __restrict__ cprev, float* __restrict__ cout,
                         int rowoff, int dup, const float* __restrict__ b_uf)
{
    int b = blockIdx.x, j = threadIdx.x;
    int id = src[soff + b];
    const float* T = g_T_iou + (size_t)id*768;
    const __half* G = g_G + (size_t)b*1792;
    float i = sigf(__half2float(G[j])       + T[j]);
    float o = sigf(__half2float(G[256+j])   + T[256+j]);
    float u = tanhfast(__half2float(G[512+j]) + T[512+j]);
    float tf = g_T_f[(size_t)id*256 + j];
    float c = i*u;
    #pragma unroll
    for (int a = 0; a < 4; a++) {
        float f = sigf(__half2float(G[768 + a*256 + j]) + b_uf[a*256+j] + tf);
        float cv;
        if (leafsrc) cv = g_lC[(size_t)__ldg(leafsrc + 4*b + a)*256 + j];
        else         cv = cprev[(size_t)(4*b+a)*256 + j];
        c += f * cv;
    }
    float h = o * tanhfast(c);
    size_t row = (size_t)(rowoff + b);
    __half hh = __float2half(h);
    g_hH[row*256 + j] = hh;
    cout[(size_t)b*256 + j] = c;
    if (dup) {
        g_hH[(row+1)*256 + j]    = hh;   // duplicate root row (attention)
        g_enc_h[(row+1)*256 + j] = h;    // fp32 root for dec_prep
    }
}

// ---------------- decoder LSTM cell + fused q@Wq@Wk (coalesced warp-dots) ----------------
__global__ void dec_prep(const float* __restrict__ emb, const int* __restrict__ tgt, int tbase,
                         const float* __restrict__ h_last, const float* __restrict__ c_last,
                         const float* __restrict__ W_ih, const float* __restrict__ b_ih,
                         const float* __restrict__ W_hh, const float* __restrict__ b_hh,
                         const float* __restrict__ Wq,   const float* __restrict__ Wk,
                         float* __restrict__ hn_out, float* __restrict__ cn_out,
                         float* __restrict__ qk_out)
{
    __shared__ float sx[256], sh[256], sg[1024], shn[256], sq[256];
    int j = threadIdx.x, bb = blockIdx.x;
    int warp = j >> 5, lane = j & 31;

    #pragma unroll
    for (int i = 0; i < 4; i++) g_w[i*256 + j] = 0.f;
    if (j < 4) g_sum[j] = 0.f;

    int sym = tgt[tbase + bb];
    sx[j] = emb[(size_t)sym*256 + j];
    sh[j] = h_last[j];
    __syncthreads();

    for (int r = warp; r < 1024; r += 8) {
        float acc = wdot256(reinterpret_cast<const float4*>(W_ih + (size_t)r*256),
                            reinterpret_cast<const float4*>(sx), lane)
                  + wdot256(reinterpret_cast<const float4*>(W_hh + (size_t)r*256),
                            reinterpret_cast<const float4*>(sh), lane);
        if (lane == 0) sg[r] = acc + b_ih[r] + b_hh[r];
    }
    __syncthreads();

    float cn = sigf(sg[256+j])*c_last[j] + sigf(sg[j])*tanhfast(sg[512+j]);
    float hn = sigf(sg[768+j])*tanhfast(cn);
    shn[j] = hn;
    hn_out[bb*256+j] = hn;
    cn_out[bb*256+j] = cn;
    __syncthreads();

    for (int r = warp; r < 256; r += 8) {
        float acc = wdot256(reinterpret_cast<const float4*>(Wq + (size_t)r*256),
                            reinterpret_cast<const float4*>(shn), lane);
        if (lane == 0) sq[r] = acc;
    }
    __syncthreads();

    float qk = 0.f;
    for (int k = 0; k < 256; k++) qk += sq[k]*Wk[(size_t)k*256 + j];
    qk_out[bb*256+j] = qk;
}

// row pointer (fp16): leaves gathered from the per-symbol table, interior from g_hH
__device__ __forceinline__ const __half* attn_row16(int r, const int* __restrict__ src){
    if (r < NLEAF) return g_lHh + (size_t)__ldg(src + LEAF_SOFF + r)*256;
    return g_hH + (size_t)r*256;
}

// ---------------- one-pass attention (fp16 h reads) ----------------
#define FROWS 512
__global__ void attn_fused(const float* __restrict__ qk, int B, const int* __restrict__ src)
{
    __shared__ float sqk[4*256];
    __shared__ float swsum[8][256];
    __shared__ float sesum[8][4];
    int tid = threadIdx.x;
    for (int i = tid; i < B*256; i += 256) sqk[i] = qk[i];
    __syncthreads();
    int warp = tid >> 5, lane = tid & 31;
    int start = blockIdx.x * FROWS;
    int end = min(NROWS, start + FROWS);

    float wacc[4][8];
    float esum[4] = {0.f, 0.f, 0.f, 0.f};
    #pragma unroll
    for (int b = 0; b < 4; b++)
        #pragma unroll
        for (int q = 0; q < 8; q++) wacc[b][q] = 0.f;

    for (int r = start + warp; r < end; r += 8) {
        // load 8 halves (16B) for this lane's 8 columns
        uint4 raw = reinterpret_cast<const uint4*>(attn_row16(r, src))[lane];
        __half2 h2[4];
        *reinterpret_cast<uint4*>(h2) = raw;
        float2 f0 = __half22float2(h2[0]);
        float2 f1 = __half22float2(h2[1]);
        float2 f2 = __half22float2(h2[2]);
        float2 f3 = __half22float2(h2[3]);
        float v[8] = {f0.x, f0.y, f1.x, f1.y, f2.x, f2.y, f3.x, f3.y};
        #pragma unroll 4
        for (int b = 0; b < 4; b++) {
            if (b >= B) break;
            const float* q = sqk + b*256 + lane*8;
            float s = v[0]*q[0]+v[1]*q[1]+v[2]*q[2]+v[3]*q[3]
                    + v[4]*q[4]+v[5]*q[5]+v[6]*q[6]+v[7]*q[7];
            #pragma unroll
            for (int off = 16; off; off >>= 1) s += __shfl_xor_sync(0xffffffffu, s, off);
            float e = __expf(s);
            if (lane == 0) esum[b] += e;
            #pragma unroll
            for (int qq = 0; qq < 8; qq++) wacc[b][qq] += e*v[qq];
        }
    }
    if (lane == 0)
        #pragma unroll
        for (int b = 0; b < 4; b++) sesum[warp][b] = esum[b];

    for (int b = 0; b < B; b++) {
        __syncthreads();
        #pragma unroll
        for (int q = 0; q < 8; q++) swsum[warp][lane*8 + q] = wacc[b][q];
        __syncthreads();
        float s = 0.f;
        #pragma unroll
        for (int w = 0; w < 8; w++) s += swsum[w][tid];
        atomicAdd(&g_w[b*256 + tid], s);
    }
    __syncthreads();
    if (tid < B) {
        float s = 0.f;
        #pragma unroll
        for (int w = 0; w < 8; w++) s += sesum[w][tid];
        atomicAdd(&g_sum[tid], s);
    }
}

// ---------------- decoder finalize (coalesced warp-dots) ----------------
__global__ void dec_fin(const float* __restrict__ hn, int is_root,
                        const float* __restrict__ Wv, const float* __restrict__ linW,
                        const float* __restrict__ linb, const float* __restrict__ pos)
{
    __shared__ float sfull[512];              // [hn | ctx]
    __shared__ float swb[256], sho[256];
    int b = blockIdx.x, j = threadIdx.x;
    int warp = j >> 5, lane = j & 31;
    swb[j] = g_w[b*256+j] / g_sum[b];
    sfull[j] = hn[b*256+j];
    __syncthreads();

    for (int r = warp; r < 256; r += 8) {
        float acc = wdot256(reinterpret_cast<const float4*>(Wv + (size_t)r*256),
                            reinterpret_cast<const float4*>(swb), lane);
        if (lane == 0) sfull[256 + r] = acc;
    }
    __syncthreads();

    for (int r = warp; r < 256; r += 8) {
        const float4* lw = reinterpret_cast<const float4*>(linW + (size_t)r*512);
        const float4* a4 = reinterpret_cast<const float4*>(sfull);
        float acc = 0.f;
        #pragma unroll
        for (int i = 0; i < 4; i++) {
            float4 wv = lw[lane + i*32];
            float4 av = a4[lane + i*32];
            acc += wv.x*av.x + wv.y*av.y + wv.z*av.z + wv.w*av.w;
        }
        #pragma unroll
        for (int off = 16; off; off >>= 1) acc += __shfl_xor_sync(0xffffffffu, acc, off);
        if (lane == 0) sho[r] = acc;
    }
    __syncthreads();

    float ho = sho[j] + linb[j];
    if (is_root) {
        g_hr[j] = ho;
        #pragma unroll
        for (int a = 0; a < 4; a++) g_rows[a*256+j] = ho + pos[a*256+j];
    } else {
        #pragma unroll
        for (int a = 0; a < 4; a++) g_rows[(4 + b*4 + a)*256 + j] = ho + pos[a*256+j];
    }
}

// ---------------- vocab projection (warp per output, n split 4-way) ----------------
__global__ void out_proj(const float* __restrict__ Wout, const float* __restrict__ bout,
                         float* __restrict__ out)
{
    __shared__ float sr[256];
    int j = threadIdx.x;
    int m = blockIdx.y;
    int warp = j >> 5, lane = j & 31;
    sr[j] = g_rows[m*256 + j];
    __syncthreads();
    int nstart = blockIdx.x * 250;
    int nend = min(1000, nstart + 250);
    for (int n = nstart + warp; n < nend; n += 8) {
        float acc = wdot256(reinterpret_cast<const float4*>(Wout + (size_t)n*256),
                            reinterpret_cast<const float4*>(sr), lane);
        if (lane == 0) out[m*1000 + n] = acc + bout[n];
    }
}

// ---------------------------------------------------------------------------
extern "C" void kernel_launch(void* const* d_in, const int* in_sizes, int n_in,
                              void* d_out, int out_size)
{
    const int*   src    = (const int*)  d_in[0];
    const int*   tgt    = (const int*)  d_in[1];
    const float* emb    = (const float*)d_in[2];
    const float* h0     = (const float*)d_in[3];
    const float* c0     = (const float*)d_in[4];
    const float* W_iou  = (const float*)d_in[5];
    const float* b_iou  = (const float*)d_in[6];
    const float* U_iou  = (const float*)d_in[7];
    const float* b_uiou = (const float*)d_in[8];
    const float* W_f    = (const float*)d_in[9];
    const float* b_wf   = (const float*)d_in[10];
    const float* U_f    = (const float*)d_in[11];
    const float* b_uf   = (const float*)d_in[12];
    const float* W_ih   = (const float*)d_in[13];
    const float* b_ih   = (const float*)d_in[14];
    const float* W_hh   = (const float*)d_in[15];
    const float* b_hh   = (const float*)d_in[16];
    const float* Wq     = (const float*)d_in[17];
    const float* Wk     = (const float*)d_in[18];
    const float* Wv     = (const float*)d_in[19];
    const float* lin_W  = (const float*)d_in[20];
    const float* lin_b  = (const float*)d_in[21];
    const float* pos    = (const float*)d_in[22];
    const float* W_out  = (const float*)d_in[23];
    const float* b_out  = (const float*)d_in[24];
    float* out = (float*)d_out;

    static bool attr_done = false;
    if (!attr_done) {
        cudaFuncSetAttribute(gemm_f16, cudaFuncAttributeMaxDynamicSharedMemorySize, SMEMB);
        attr_done = true;
    }

    float *pEnc,*pCA,*pCB;
    float *pHnR,*pCnR,*pQkR,*pHnC,*pCnC,*pQkC,*pHr;
    __half *pHH,*pLHh,*pG;
    cudaGetSymbolAddress((void**)&pEnc,  g_enc_h);
    cudaGetSymbolAddress((void**)&pHH,   g_hH);
    cudaGetSymbolAddress((void**)&pLHh,  g_lHh);
    cudaGetSymbolAddress((void**)&pCA,   g_cA);
    cudaGetSymbolAddress((void**)&pCB,   g_cB);
    cudaGetSymbolAddress((void**)&pG,    g_G);
    cudaGetSymbolAddress((void**)&pHnR,  g_hn_r);
    cudaGetSymbolAddress((void**)&pCnR,  g_cn_r);
    cudaGetSymbolAddress((void**)&pQkR,  g_qk_r);
    cudaGetSymbolAddress((void**)&pHnC,  g_hn_c);
    cudaGetSymbolAddress((void**)&pCnC,  g_cn_c);
    cudaGetSymbolAddress((void**)&pQkC,  g_qk_c);
    cudaGetSymbolAddress((void**)&pHr,   g_hr);

    static const int pow4[10] = {1,4,16,64,256,1024,4096,16384,65536,262144};
    auto rowoff = [&](int l){ return (262144 - pow4[l+1]) / 3; };
    auto soff   = [&](int l){ return (pow4[l] - 1) / 3; };

    // prep (3 launches so launch #4 = level-7 gemm — the ncu capture target)
    prep_tables<<<dim3(8, 8), 256>>>(emb, W_iou, b_iou, b_uiou, W_f, b_wf);
    pack_U_consts<<<1792, 256>>>(U_iou, U_f, h0, b_uf);
    leaf_tab<<<1000, 256>>>(c0);

    // interior levels bottom-up — all levels on the fp16 mma GEMM
    float* cprev = pCA;
    float* cout  = pCB;
    for (int l = 7; l >= 0; l--) {
        int B = pow4[l];
        if (l == 7) {
            gemm_f16<<<dim3(GN/TN, (B+TM-1)/TM), 256, SMEMB>>>(pLHh, src + LEAF_SOFF, pG, B);
            level_ew<<<B, 256>>>(src, soff(l), src + LEAF_SOFF, nullptr, cout,
                                 rowoff(l), 0, b_uf);
        } else {
            const __half* Ap = pHH + (size_t)rowoff(l+1)*256;
            gemm_f16<<<dim3(GN/TN, (B+TM-1)/TM), 256, SMEMB>>>(Ap, nullptr, pG, B);
            level_ew<<<B, 256>>>(src, soff(l), nullptr, cprev, cout,
                                 rowoff(l), (l == 0) ? 1 : 0, b_uf);
        }
        float* t = cprev; cprev = cout; cout = t;
    }

    int fgrid = (NROWS + FROWS - 1) / FROWS;

    // root decode step
    dec_prep<<<1, 256>>>(emb, tgt, 0, pEnc + (size_t)(NROWS-1)*256, cprev,
                         W_ih, b_ih, W_hh, b_hh, Wq, Wk, pHnR, pCnR, pQkR);
    attn_fused<<<fgrid, 256>>>(pQkR, 1, src);
    dec_fin<<<1, 256>>>(pHnR, 1, Wv, lin_W, lin_b, pos);

    // child decode step (B=4)
    dec_prep<<<4, 256>>>(emb, tgt, 1, pHr, pCnR,
                         W_ih, b_ih, W_hh, b_hh, Wq, Wk, pHnC, pCnC, pQkC);
    attn_fused<<<fgrid, 256>>>(pQkC, 4, src);
    dec_fin<<<4, 256>>>(pHnC, 0, Wv, lin_W, lin_b, pos);

    // vocab projection
    out_proj<<<dim3(4, 20), 256>>>(W_out, b_out, out);
}

// round 17
// speedup vs baseline: 1.0533x; 1.0523x over previous
#include <cuda_runtime.h>
#include <cuda_fp16.h>
#include <cstdint>

#define NROWS 87382          // 87381 nodes + duplicated root
#define NLEAF 65536
#define LEAF_SOFF 21845

#define GN 1792
#define GK 1024

// ---- fp16 mma GEMM: CTA 128x128, 8 warps (32x64), KC=32, 4-stage, 2 CTAs/SM ----
#define TM 128
#define TN 128
#define KC 32
#define NCH (GK/KC)           // 32
#define NST 4
#define ROWW 20               // uint32 words per row: 16 data (32 halves) + 4 pad
#define A_OFF 0
#define U_OFF (128*ROWW)
#define STG (256*ROWW)        // 5120 words per stage
#define SMEMB (NST*STG*4)     // 81920 B
#define CPAD 136              // halves per staged C row

// ---------------- device scratch (no allocations allowed) ----------------
__device__ float g_T_iou[1000*768];
__device__ float g_T_f[1000*256];
__device__ float g_uiou0[768];
__device__ float g_uf0[1024];
__device__ float g_lC[1000*256];                       // leaf c per symbol
__device__ __align__(16) __half g_lHh[1000*256];       // leaf h per symbol (fp16)
__device__ __align__(16) __half g_Uh[1792*1024];       // packed U fp16
__device__ float g_enc_h[(size_t)NROWS*256];           // fp32: only root dup row used
__device__ __align__(16) __half g_hH[(size_t)NROWS*256]; // fp16 interior h (gemm A + attn)
__device__ float g_cA[(size_t)16384*256];
__device__ float g_cB[(size_t)16384*256];
__device__ __align__(16) __half g_G[(size_t)16384*1792];  // gate preactivations (fp16)
__device__ float g_w[4*256];
__device__ float g_sum[4];
__device__ float g_hn_r[256];
__device__ float g_cn_r[256];
__device__ float g_qk_r[256];
__device__ float g_hn_c[4*256];
__device__ float g_cn_c[4*256];
__device__ float g_qk_c[4*256];
__device__ float g_hr[256];
__device__ float g_rows[20*256];

__device__ __forceinline__ float sigf(float x){ return 1.f/(1.f+__expf(-x)); }
__device__ __forceinline__ float tanhfast(float x){ return 1.f - 2.f/(__expf(2.f*x)+1.f); }

__device__ __forceinline__ void cpasync16p(uint32_t dst, const void* src, bool p){
    int sz = p ? 16 : 0;
    asm volatile("cp.async.cg.shared.global [%0], [%1], 16, %2;\n"
                 :: "r"(dst), "l"(src), "r"(sz));
}
__device__ __forceinline__ void cp_commit(){ asm volatile("cp.async.commit_group;\n"); }
template<int N> __device__ __forceinline__ void cp_wait(){ asm volatile("cp.async.wait_group %0;\n" :: "n"(N)); }

__device__ __forceinline__ void mma_f16(float* d, const uint32_t* a, const uint32_t* b){
    asm volatile(
        "mma.sync.aligned.m16n8k16.row.col.f32.f16.f16.f32 "
        "{%0,%1,%2,%3}, {%4,%5,%6,%7}, {%8,%9}, {%0,%1,%2,%3};"
        : "+f"(d[0]), "+f"(d[1]), "+f"(d[2]), "+f"(d[3])
        : "r"(a[0]), "r"(a[1]), "r"(a[2]), "r"(a[3]), "r"(b[0]), "r"(b[1]));
}

__device__ __forceinline__ void ldsm4(uint32_t& r0, uint32_t& r1, uint32_t& r2, uint32_t& r3,
                                      uint32_t addr){
    asm volatile("ldmatrix.sync.aligned.m8n8.x4.shared.b16 {%0,%1,%2,%3}, [%4];"
        : "=r"(r0), "=r"(r1), "=r"(r2), "=r"(r3) : "r"(addr));
}

// warp-dot helper: 256-float dot (a in smem, w in gmem), lane-strided float4
__device__ __forceinline__ float wdot256(const float4* __restrict__ w,
                                         const float4* __restrict__ a, int lane){
    float acc = 0.f;
    #pragma unroll
    for (int i = 0; i < 2; i++) {
        float4 wv = w[lane + i*32];
        float4 av = a[lane + i*32];
        acc += wv.x*av.x + wv.y*av.y + wv.z*av.z + wv.w*av.w;
    }
    #pragma unroll
    for (int off = 16; off; off >>= 1) acc += __shfl_xor_sync(0xffffffffu, acc, off);
    return acc;
}

// ---------------- fp16 GEMM: G[M,1792] = A[M,1024] @ Uh^T (128x128, 2 CTA/SM) ----------------
__global__ void __launch_bounds__(256, 2) gemm_f16(
    const __half* __restrict__ Ah, const int* __restrict__ aidx,
    __half* __restrict__ C, int M)
{
    extern __shared__ uint32_t smw[];

    const int tid  = threadIdx.x;
    const int lane = tid & 31;
    const int wid  = tid >> 5;
    const int warp_m = wid & 3;          // 32-row slab
    const int warp_n = wid >> 2;         // 64-col slab

    const int m0 = blockIdx.y * TM;
    const int n0 = blockIdx.x * TN;

    const int role = tid >> 7;           // 0: A rows, 1: U rows
    const int lrow = tid & 127;
    const bool arow_ok = (m0 + lrow) < M;

    uint32_t sb = (uint32_t)__cvta_generic_to_shared(smw);
    uint32_t dst = sb + ((role ? U_OFF : A_OFF) + lrow*ROWW)*4;

    const __half* Urow = g_Uh + (size_t)(n0 + lrow)*GK;

    const int mi = lane >> 3, rr = lane & 7;
    const uint32_t loff = (uint32_t)((((mi & 1)*8 + rr)*ROWW)*4 + (mi >> 1)*16);

    auto issue = [&](int ch, int slot){
        uint32_t so = slot * (STG*4);
        const __half* gsrc;
        bool p;
        if (role == 0) {
            if (aidx) {
                int a = ch >> 3;
                int id = arow_ok ? __ldg(aidx + (size_t)(m0 + lrow)*4 + a) : 0;
                gsrc = Ah + (size_t)id*256 + ((ch*KC) & 255);
            } else {
                gsrc = Ah + (size_t)(m0 + lrow)*GK + ch*KC;
            }
            p = arow_ok;
        } else {
            gsrc = Urow + ch*KC;
            p = true;
        }
        #pragma unroll
        for (int c = 0; c < 4; c++) cpasync16p(so + dst + c*16, gsrc + c*8, p);
        cp_commit();
    };

    #pragma unroll
    for (int s = 0; s < NST-1; s++) issue(s, s);

    float acc[2][8][4];
    #pragma unroll
    for (int mt = 0; mt < 2; mt++)
        #pragma unroll
        for (int nt = 0; nt < 8; nt++)
            #pragma unroll
            for (int q = 0; q < 4; q++) acc[mt][nt][q] = 0.f;

    for (int i = 0; i < NCH; i++) {
        cp_wait<NST-2>();
        __syncthreads();

        int nx = i + NST - 1;
        if (nx < NCH) issue(nx, nx % NST);
        else cp_commit();

        const uint32_t stg = sb + (i % NST)*(STG*4);

        #pragma unroll
        for (int ks = 0; ks < 2; ks++) {
            const uint32_t kb = ks*32;
            uint32_t af[2][4], bf[8][2];
            #pragma unroll
            for (int mt = 0; mt < 2; mt++)
                ldsm4(af[mt][0], af[mt][1], af[mt][2], af[mt][3],
                      stg + (uint32_t)((warp_m*32 + mt*16)*ROWW)*4 + kb + loff);
            #pragma unroll
            for (int ntp = 0; ntp < 4; ntp++) {
                uint32_t r0, r1, r2, r3;
                ldsm4(r0, r1, r2, r3,
                      stg + (uint32_t)(U_OFF + (warp_n*64 + ntp*16)*ROWW)*4 + kb + loff);
                bf[2*ntp][0]   = r0;
                bf[2*ntp+1][0] = r1;
                bf[2*ntp][1]   = r2;
                bf[2*ntp+1][1] = r3;
            }
            #pragma unroll
            for (int mt = 0; mt < 2; mt++)
                #pragma unroll
                for (int nt = 0; nt < 8; nt++)
                    mma_f16(acc[mt][nt], af[mt], bf[nt]);
        }
    }

    // ---- coalesced epilogue ----
    cp_wait<0>();
    __syncthreads();
    __half* Cs = reinterpret_cast<__half*>(smw);
    const int g  = lane >> 2;
    const int tq = lane & 3;
    #pragma unroll
    for (int mt = 0; mt < 2; mt++) {
        int rm = warp_m*32 + mt*16 + g;
        #pragma unroll
        for (int nt = 0; nt < 8; nt++) {
            int cn = warp_n*64 + nt*8 + tq*2;
            *reinterpret_cast<__half2*>(Cs + rm*CPAD + cn)
                = __floats2half2_rn(acc[mt][nt][0], acc[mt][nt][1]);
            *reinterpret_cast<__half2*>(Cs + (rm+8)*CPAD + cn)
                = __floats2half2_rn(acc[mt][nt][2], acc[mt][nt][3]);
        }
    }
    __syncthreads();
    #pragma unroll
    for (int it = 0; it < 8; it++) {
        int idx = it*256 + tid;          // 0..2047
        int r  = idx >> 4;               // row 0..127
        int cc = (idx & 15) * 8;
        if (m0 + r < M) {
            const uint4 v = *reinterpret_cast<const uint4*>(Cs + r*CPAD + cc);
            *reinterpret_cast<uint4*>(C + (size_t)(m0+r)*GN + n0 + cc) = v;
        }
    }
}

// ---------------- merged prep GEMM: T_iou + T_f ----------------
__global__ void __launch_bounds__(256, 2) prep_tables(
    const float* __restrict__ emb,
    const float* __restrict__ W_iou, const float* __restrict__ b_iou,
    const float* __restrict__ b_uiou,
    const float* __restrict__ W_f,   const float* __restrict__ b_wf)
{
    __shared__ float As[16][128];
    __shared__ float Ws[16][128];
    const int tid  = threadIdx.x;
    const int m0   = blockIdx.y * 128;

    const float* W; const float* bias; const float* bias2; float* Cc; int N; int n0;
    if (blockIdx.x < 6) { W = W_iou; bias = b_iou; bias2 = b_uiou; Cc = g_T_iou; N = 768; n0 = blockIdx.x*128; }
    else                { W = W_f;   bias = b_wf;  bias2 = nullptr; Cc = g_T_f; N = 256; n0 = (blockIdx.x-6)*128; }

    const int M = 1000, K = 256;
    const int trow = (tid >> 4) << 3;
    const int tcol = (tid & 15) << 3;
    const int lm   = tid >> 2;
    const int lk   = (tid & 3) << 2;

    float acc[8][8];
    #pragma unroll
    for (int i = 0; i < 8; i++)
        #pragma unroll
        for (int j = 0; j < 8; j++) acc[i][j] = 0.f;

    for (int k0 = 0; k0 < K; k0 += 16) {
        #pragma unroll
        for (int h = 0; h < 2; h++) {
            int m = m0 + lm + h*64;
            float4 v = make_float4(0.f,0.f,0.f,0.f);
            if (m < M) v = *reinterpret_cast<const float4*>(emb + (size_t)m*K + k0 + lk);
            As[lk+0][lm+h*64] = v.x; As[lk+1][lm+h*64] = v.y;
            As[lk+2][lm+h*64] = v.z; As[lk+3][lm+h*64] = v.w;

            int n = n0 + lm + h*64;
            float4 w = make_float4(0.f,0.f,0.f,0.f);
            if (n < N) w = *reinterpret_cast<const float4*>(W + (size_t)n*K + k0 + lk);
            Ws[lk+0][lm+h*64] = w.x; Ws[lk+1][lm+h*64] = w.y;
            Ws[lk+2][lm+h*64] = w.z; Ws[lk+3][lm+h*64] = w.w;
        }
        __syncthreads();
        #pragma unroll
        for (int kk = 0; kk < 16; kk++) {
            float ra[8], rw[8];
            #pragma unroll
            for (int i = 0; i < 8; i++) ra[i] = As[kk][trow+i];
            #pragma unroll
            for (int j = 0; j < 8; j++) rw[j] = Ws[kk][tcol+j];
            #pragma unroll
            for (int i = 0; i < 8; i++)
                #pragma unroll
                for (int j = 0; j < 8; j++) acc[i][j] += ra[i]*rw[j];
        }
        __syncthreads();
    }
    #pragma unroll
    for (int i = 0; i < 8; i++) {
        int m = m0 + trow + i;
        if (m >= M) break;
        #pragma unroll
        for (int j = 0; j < 8; j++) {
            int n = n0 + tcol + j;
            float b = bias[n];
            if (bias2) b += bias2[n];
            Cc[(size_t)m*N + n] = acc[i][j] + b;
        }
    }
}

// ---------------- pack U + leaf constants ----------------
__global__ void pack_U_consts(const float* __restrict__ U_iou, const float* __restrict__ U_f,
                              const float* __restrict__ h0,    const float* __restrict__ b_uf)
{
    int idx = blockIdx.x * 256 + threadIdx.x;
    int r = idx / 256;
    int c4 = idx % 256;
    const float4* srcp;
    if (r < 768) srcp = reinterpret_cast<const float4*>(U_iou + (size_t)r*1024) + c4;
    else         srcp = reinterpret_cast<const float4*>(U_f   + (size_t)(r-768)*1024) + c4;
    float4 v = *srcp;
    size_t o = (size_t)r*1024 + c4*4;
    g_Uh[o+0] = __float2half(v.x); g_Uh[o+1] = __float2half(v.y);
    g_Uh[o+2] = __float2half(v.z); g_Uh[o+3] = __float2half(v.w);

    if (blockIdx.x < 224) {
        int lane = threadIdx.x & 31;
        int w = blockIdx.x * 8 + (threadIdx.x >> 5);
        const float* u = (w < 768) ? (U_iou + (size_t)w*1024) : (U_f + (size_t)(w-768)*1024);
        const float4* u4 = reinterpret_cast<const float4*>(u);
        const float4* h4 = reinterpret_cast<const float4*>(h0);
        float acc = 0.f;
        #pragma unroll
        for (int i = 0; i < 8; i++) {
            float4 uv = u4[lane + i*32];
            float4 hv = h4[lane + i*32];
            acc += uv.x*hv.x + uv.y*hv.y + uv.z*hv.z + uv.w*hv.w;
        }
        #pragma unroll
        for (int off = 16; off; off >>= 1) acc += __shfl_xor_sync(0xffffffffu, acc, off);
        if (lane == 0) {
            if (w < 768) g_uiou0[w] = acc;
            else g_uf0[w-768] = acc + b_uf[w-768];
        }
    }
}

// ---------------- small-M GEMM (B<=64): fp16 warp-per-column ----------------
__global__ void small_gemm16(const __half* __restrict__ A, __half* __restrict__ C)
{
    __shared__ float sh[1024];
    int tid = threadIdx.x, lane = tid & 31, wid = tid >> 5;
    int m = blockIdx.y;
    // stage A row (1024 halves) as floats
    for (int i = tid; i < 512; i += 256) {
        float2 f = __half22float2(reinterpret_cast<const __half2*>(A + (size_t)m*1024)[i]);
        sh[2*i] = f.x; sh[2*i+1] = f.y;
    }
    __syncthreads();
    int ntile = blockIdx.x * 256;
    for (int n = ntile + wid; n < ntile + 256; n += 8) {
        const uint4* u = reinterpret_cast<const uint4*>(g_Uh + (size_t)n*1024);
        float acc = 0.f;
        #pragma unroll
        for (int i = 0; i < 4; i++) {
            uint4 raw = u[lane + i*32];
            __half2 h2[4];
            *reinterpret_cast<uint4*>(h2) = raw;
            float2 a = __half22float2(h2[0]);
            float2 b = __half22float2(h2[1]);
            float2 c2 = __half22float2(h2[2]);
            float2 d = __half22float2(h2[3]);
            const float* s = sh + (size_t)(lane + i*32)*8;
            acc += a.x*s[0] + a.y*s[1] + b.x*s[2] + b.y*s[3]
                 + c2.x*s[4] + c2.y*s[5] + d.x*s[6] + d.y*s[7];
        }
        #pragma unroll
        for (int off = 16; off; off >>= 1) acc += __shfl_xor_sync(0xffffffffu, acc, off);
        if (lane == 0) C[(size_t)m*GN + n] = __float2half(acc);
    }
}

// ---------------- per-symbol leaf tables (h fp16, c fp32) ----------------
__global__ void leaf_tab(const float* __restrict__ c0)
{
    int s = blockIdx.x, j = threadIdx.x;
    const float* T = g_T_iou + (size_t)s*768;
    float i = sigf(T[j]       + g_uiou0[j]);
    float o = sigf(T[256+j]   + g_uiou0[256+j]);
    float u = tanhfast(T[512+j] + g_uiou0[512+j]);
    float tf = g_T_f[(size_t)s*256 + j];
    float c = i*u;
    #pragma unroll
    for (int a = 0; a < 4; a++) {
        float f = sigf(g_uf0[a*256+j] + tf);
        c += f * c0[a*256+j];
    }
    float h = o * tanhfast(c);
    g_lHh[(size_t)s*256 + j] = __float2half(h);
    g_lC[(size_t)s*256 + j]  = c;
}

// ---------------- interior level: combine GEMM result (fp16) + gates ----------------
__global__ void level_ew(const int* __restrict__ src, int soff,
                         const int* __restrict__ leafsrc,
                         const float* __restrict__ cprev, float* __restrict__ cout,
                         int rowoff, int dup, const float* __restrict__ b_uf)
{
    int b = blockIdx.x, j = threadIdx.x;
    int id = src[soff + b];
    const float* T = g_T_iou + (size_t)id*768;
    const __half* G = g_G + (size_t)b*1792;
    float i = sigf(__half2float(G[j])       + T[j]);
    float o = sigf(__half2float(G[256+j])   + T[256+j]);
    float u = tanhfast(__half2float(G[512+j]) + T[512+j]);
    float tf = g_T_f[(size_t)id*256 + j];
    float c = i*u;
    #pragma unroll
    for (int a = 0; a < 4; a++) {
        float f = sigf(__half2float(G[768 + a*256 + j]) + b_uf[a*256+j] + tf);
        float cv;
        if (leafsrc) cv = g_lC[(size_t)__ldg(leafsrc + 4*b + a)*256 + j];
        else         cv = cprev[(size_t)(4*b+a)*256 + j];
        c += f * cv;
    }
    float h = o * tanhfast(c);
    size_t row = (size_t)(rowoff + b);
    __half hh = __float2half(h);
    g_hH[row*256 + j] = hh;
    cout[(size_t)b*256 + j] = c;
    if (dup) {
        g_hH[(row+1)*256 + j]    = hh;   // duplicate root row (attention)
        g_enc_h[(row+1)*256 + j] = h;    // fp32 root for dec_prep
    }
}

// ---------------- decoder LSTM cell + fused q@Wq@Wk (coalesced warp-dots) ----------------
__global__ void dec_prep(const float* __restrict__ emb, const int* __restrict__ tgt, int tbase,
                         const float* __restrict__ h_last, const float* __restrict__ c_last,
                         const float* __restrict__ W_ih, const float* __restrict__ b_ih,
                         const float* __restrict__ W_hh, const float* __restrict__ b_hh,
                         const float* __restrict__ Wq,   const float* __restrict__ Wk,
                         float* __restrict__ hn_out, float* __restrict__ cn_out,
                         float* __restrict__ qk_out)
{
    __shared__ float sx[256], sh[256], sg[1024], shn[256], sq[256];
    int j = threadIdx.x, bb = blockIdx.x;
    int warp = j >> 5, lane = j & 31;

    #pragma unroll
    for (int i = 0; i < 4; i++) g_w[i*256 + j] = 0.f;
    if (j < 4) g_sum[j] = 0.f;

    int sym = tgt[tbase + bb];
    sx[j] = emb[(size_t)sym*256 + j];
    sh[j] = h_last[j];
    __syncthreads();

    for (int r = warp; r < 1024; r += 8) {
        float acc = wdot256(reinterpret_cast<const float4*>(W_ih + (size_t)r*256),
                            reinterpret_cast<const float4*>(sx), lane)
                  + wdot256(reinterpret_cast<const float4*>(W_hh + (size_t)r*256),
                            reinterpret_cast<const float4*>(sh), lane);
        if (lane == 0) sg[r] = acc + b_ih[r] + b_hh[r];
    }
    __syncthreads();

    float cn = sigf(sg[256+j])*c_last[j] + sigf(sg[j])*tanhfast(sg[512+j]);
    float hn = sigf(sg[768+j])*tanhfast(cn);
    shn[j] = hn;
    hn_out[bb*256+j] = hn;
    cn_out[bb*256+j] = cn;
    __syncthreads();

    for (int r = warp; r < 256; r += 8) {
        float acc = wdot256(reinterpret_cast<const float4*>(Wq + (size_t)r*256),
                            reinterpret_cast<const float4*>(shn), lane);
        if (lane == 0) sq[r] = acc;
    }
    __syncthreads();

    float qk = 0.f;
    for (int k = 0; k < 256; k++) qk += sq[k]*Wk[(size_t)k*256 + j];
    qk_out[bb*256+j] = qk;
}

// row pointer (fp16): leaves gathered from the per-symbol table, interior from g_hH
__device__ __forceinline__ const __half* attn_row16(int r, const int* __restrict__ src){
    if (r < NLEAF) return g_lHh + (size_t)__ldg(src + LEAF_SOFF + r)*256;
    return g_hH + (size_t)r*256;
}

// ---------------- one-pass attention (fp16 h reads) ----------------
#define FROWS 512
__global__ void attn_fused(const float* __restrict__ qk, int B, const int* __restrict__ src)
{
    __shared__ float sqk[4*256];
    __shared__ float swsum[8][256];
    __shared__ float sesum[8][4];
    int tid = threadIdx.x;
    for (int i = tid; i < B*256; i += 256) sqk[i] = qk[i];
    __syncthreads();
    int warp = tid >> 5, lane = tid & 31;
    int start = blockIdx.x * FROWS;
    int end = min(NROWS, start + FROWS);

    float wacc[4][8];
    float esum[4] = {0.f, 0.f, 0.f, 0.f};
    #pragma unroll
    for (int b = 0; b < 4; b++)
        #pragma unroll
        for (int q = 0; q < 8; q++) wacc[b][q] = 0.f;

    for (int r = start + warp; r < end; r += 8) {
        uint4 raw = reinterpret_cast<const uint4*>(attn_row16(r, src))[lane];
        __half2 h2[4];
        *reinterpret_cast<uint4*>(h2) = raw;
        float2 f0 = __half22float2(h2[0]);
        float2 f1 = __half22float2(h2[1]);
        float2 f2 = __half22float2(h2[2]);
        float2 f3 = __half22float2(h2[3]);
        float v[8] = {f0.x, f0.y, f1.x, f1.y, f2.x, f2.y, f3.x, f3.y};
        #pragma unroll 4
        for (int b = 0; b < 4; b++) {
            if (b >= B) break;
            const float* q = sqk + b*256 + lane*8;
            float s = v[0]*q[0]+v[1]*q[1]+v[2]*q[2]+v[3]*q[3]
                    + v[4]*q[4]+v[5]*q[5]+v[6]*q[6]+v[7]*q[7];
            #pragma unroll
            for (int off = 16; off; off >>= 1) s += __shfl_xor_sync(0xffffffffu, s, off);
            float e = __expf(s);
            if (lane == 0) esum[b] += e;
            #pragma unroll
            for (int qq = 0; qq < 8; qq++) wacc[b][qq] += e*v[qq];
        }
    }
    if (lane == 0)
        #pragma unroll
        for (int b = 0; b < 4; b++) sesum[warp][b] = esum[b];

    for (int b = 0; b < B; b++) {
        __syncthreads();
        #pragma unroll
        for (int q = 0; q < 8; q++) swsum[warp][lane*8 + q] = wacc[b][q];
        __syncthreads();
        float s = 0.f;
        #pragma unroll
        for (int w = 0; w < 8; w++) s += swsum[w][tid];
        atomicAdd(&g_w[b*256 + tid], s);
    }
    __syncthreads();
    if (tid < B) {
        float s = 0.f;
        #pragma unroll
        for (int w = 0; w < 8; w++) s += sesum[w][tid];
        atomicAdd(&g_sum[tid], s);
    }
}

// ---------------- decoder finalize (coalesced warp-dots) ----------------
__global__ void dec_fin(const float* __restrict__ hn, int is_root,
                        const float* __restrict__ Wv, const float* __restrict__ linW,
                        const float* __restrict__ linb, const float* __restrict__ pos)
{
    __shared__ float sfull[512];              // [hn | ctx]
    __shared__ float swb[256], sho[256];
    int b = blockIdx.x, j = threadIdx.x;
    int warp = j >> 5, lane = j & 31;
    swb[j] = g_w[b*256+j] / g_sum[b];
    sfull[j] = hn[b*256+j];
    __syncthreads();

    for (int r = warp; r < 256; r += 8) {
        float acc = wdot256(reinterpret_cast<const float4*>(Wv + (size_t)r*256),
                            reinterpret_cast<const float4*>(swb), lane);
        if (lane == 0) sfull[256 + r] = acc;
    }
    __syncthreads();

    for (int r = warp; r < 256; r += 8) {
        const float4* lw = reinterpret_cast<const float4*>(linW + (size_t)r*512);
        const float4* a4 = reinterpret_cast<const float4*>(sfull);
        float acc = 0.f;
        #pragma unroll
        for (int i = 0; i < 4; i++) {
            float4 wv = lw[lane + i*32];
            float4 av = a4[lane + i*32];
            acc += wv.x*av.x + wv.y*av.y + wv.z*av.z + wv.w*av.w;
        }
        #pragma unroll
        for (int off = 16; off; off >>= 1) acc += __shfl_xor_sync(0xffffffffu, acc, off);
        if (lane == 0) sho[r] = acc;
    }
    __syncthreads();

    float ho = sho[j] + linb[j];
    if (is_root) {
        g_hr[j] = ho;
        #pragma unroll
        for (int a = 0; a < 4; a++) g_rows[a*256+j] = ho + pos[a*256+j];
    } else {
        #pragma unroll
        for (int a = 0; a < 4; a++) g_rows[(4 + b*4 + a)*256 + j] = ho + pos[a*256+j];
    }
}

// ---------------- vocab projection (warp per output, n split 4-way) ----------------
__global__ void out_proj(const float* __restrict__ Wout, const float* __restrict__ bout,
                         float* __restrict__ out)
{
    __shared__ float sr[256];
    int j = threadIdx.x;
    int m = blockIdx.y;
    int warp = j >> 5, lane = j & 31;
    sr[j] = g_rows[m*256 + j];
    __syncthreads();
    int nstart = blockIdx.x * 250;
    int nend = min(1000, nstart + 250);
    for (int n = nstart + warp; n < nend; n += 8) {
        float acc = wdot256(reinterpret_cast<const float4*>(Wout + (size_t)n*256),
                            reinterpret_cast<const float4*>(sr), lane);
        if (lane == 0) out[m*1000 + n] = acc + bout[n];
    }
}

// ---------------------------------------------------------------------------
extern "C" void kernel_launch(void* const* d_in, const int* in_sizes, int n_in,
                              void* d_out, int out_size)
{
    const int*   src    = (const int*)  d_in[0];
    const int*   tgt    = (const int*)  d_in[1];
    const float* emb    = (const float*)d_in[2];
    const float* h0     = (const float*)d_in[3];
    const float* c0     = (const float*)d_in[4];
    const float* W_iou  = (const float*)d_in[5];
    const float* b_iou  = (const float*)d_in[6];
    const float* U_iou  = (const float*)d_in[7];
    const float* b_uiou = (const float*)d_in[8];
    const float* W_f    = (const float*)d_in[9];
    const float* b_wf   = (const float*)d_in[10];
    const float* U_f    = (const float*)d_in[11];
    const float* b_uf   = (const float*)d_in[12];
    const float* W_ih   = (const float*)d_in[13];
    const float* b_ih   = (const float*)d_in[14];
    const float* W_hh   = (const float*)d_in[15];
    const float* b_hh   = (const float*)d_in[16];
    const float* Wq     = (const float*)d_in[17];
    const float* Wk     = (const float*)d_in[18];
    const float* Wv     = (const float*)d_in[19];
    const float* lin_W  = (const float*)d_in[20];
    const float* lin_b  = (const float*)d_in[21];
    const float* pos    = (const float*)d_in[22];
    const float* W_out  = (const float*)d_in[23];
    const float* b_out  = (const float*)d_in[24];
    float* out = (float*)d_out;

    static bool attr_done = false;
    if (!attr_done) {
        cudaFuncSetAttribute(gemm_f16, cudaFuncAttributeMaxDynamicSharedMemorySize, SMEMB);
        attr_done = true;
    }

    float *pEnc,*pCA,*pCB;
    float *pHnR,*pCnR,*pQkR,*pHnC,*pCnC,*pQkC,*pHr;
    __half *pHH,*pLHh,*pG;
    cudaGetSymbolAddress((void**)&pEnc,  g_enc_h);
    cudaGetSymbolAddress((void**)&pHH,   g_hH);
    cudaGetSymbolAddress((void**)&pLHh,  g_lHh);
    cudaGetSymbolAddress((void**)&pCA,   g_cA);
    cudaGetSymbolAddress((void**)&pCB,   g_cB);
    cudaGetSymbolAddress((void**)&pG,    g_G);
    cudaGetSymbolAddress((void**)&pHnR,  g_hn_r);
    cudaGetSymbolAddress((void**)&pCnR,  g_cn_r);
    cudaGetSymbolAddress((void**)&pQkR,  g_qk_r);
    cudaGetSymbolAddress((void**)&pHnC,  g_hn_c);
    cudaGetSymbolAddress((void**)&pCnC,  g_cn_c);
    cudaGetSymbolAddress((void**)&pQkC,  g_qk_c);
    cudaGetSymbolAddress((void**)&pHr,   g_hr);

    static const int pow4[10] = {1,4,16,64,256,1024,4096,16384,65536,262144};
    auto rowoff = [&](int l){ return (262144 - pow4[l+1]) / 3; };
    auto soff   = [&](int l){ return (pow4[l] - 1) / 3; };

    // prep (3 launches so launch #4 = level-7 gemm — the ncu capture target)
    prep_tables<<<dim3(8, 8), 256>>>(emb, W_iou, b_iou, b_uiou, W_f, b_wf);
    pack_U_consts<<<1792, 256>>>(U_iou, U_f, h0, b_uf);
    leaf_tab<<<1000, 256>>>(c0);

    // interior levels bottom-up
    float* cprev = pCA;
    float* cout  = pCB;
    for (int l = 7; l >= 0; l--) {
        int B = pow4[l];
        if (l == 7) {
            gemm_f16<<<dim3(GN/TN, (B+TM-1)/TM), 256, SMEMB>>>(pLHh, src + LEAF_SOFF, pG, B);
            level_ew<<<B, 256>>>(src, soff(l), src + LEAF_SOFF, nullptr, cout,
                                 rowoff(l), 0, b_uf);
        } else if (B >= 256) {
            const __half* Ap = pHH + (size_t)rowoff(l+1)*256;
            gemm_f16<<<dim3(GN/TN, (B+TM-1)/TM), 256, SMEMB>>>(Ap, nullptr, pG, B);
            level_ew<<<B, 256>>>(src, soff(l), nullptr, cprev, cout,
                                 rowoff(l), 0, b_uf);
        } else {
            const __half* Ap = pHH + (size_t)rowoff(l+1)*256;
            small_gemm16<<<dim3(7, B), 256>>>(Ap, pG);
            level_ew<<<B, 256>>>(src, soff(l), nullptr, cprev, cout,
                                 rowoff(l), (l == 0) ? 1 : 0, b_uf);
        }
        float* t = cprev; cprev = cout; cout = t;
    }

    int fgrid = (NROWS + FROWS - 1) / FROWS;

    // root decode step
    dec_prep<<<1, 256>>>(emb, tgt, 0, pEnc + (size_t)(NROWS-1)*256, cprev,
                         W_ih, b_ih, W_hh, b_hh, Wq, Wk, pHnR, pCnR, pQkR);
    attn_fused<<<fgrid, 256>>>(pQkR, 1, src);
    dec_fin<<<1, 256>>>(pHnR, 1, Wv, lin_W, lin_b, pos);

    // child decode step (B=4)
    dec_prep<<<4, 256>>>(emb, tgt, 1, pHr, pCnR,
                         W_ih, b_ih, W_hh, b_hh, Wq, Wk, pHnC, pCnC, pQkC);
    attn_fused<<<fgrid, 256>>>(pQkC, 4, src);
    dec_fin<<<4, 256>>>(pHnC, 0, Wv, lin_W, lin_b, pos);

    // vocab projection
    out_proj<<<dim3(4, 20), 256>>>(W_out, b_out, out);
}